// round 17
// baseline (speedup 1.0000x reference)
#include <cuda_runtime.h>
#include <cuda_fp16.h>
#include <mma.h>
#include <math.h>
#include <stdint.h>

using namespace nvcuda;

// Problem-size maxima (fixed by the dataset: N=100000, E=1600000, F=H=128, OUT=40)
#define NMAX 100000
#define EMAX 1600000
#define FDIM 128
#define SCAN_BS 2048
#define NPAD (NMAX + 128)   // pad rows so WMMA fragment loads past n stay in-bounds

// ---------------- scratch (static device globals; no allocation) ----------------
__device__ __align__(32) __half g_bufH [(size_t)NPAD * FDIM]; // h (fp16) — gather source
__device__ __align__(32) __half g_bufO1[(size_t)NPAD * FDIM]; // out1, then s (fp16, in-place)
__device__ __align__(32) __half g_W1h[FDIM * FDIM];           // W1 fp16
__device__ __align__(32) __half g_W2h[FDIM * FDIM];           // W2 fp16
__device__ __align__(32) __half g_Wch[FDIM * 48];             // Wc fp16, padded 40->48 cols
__device__ float g_dinv[NMAX];
__device__ __align__(16) int g_cnt[NMAX + 8];
__device__ __align__(16) int g_rowstart[NMAX + 8];
__device__ __align__(16) int g_cursor[NMAX + 8];
__device__ int   g_csrc[EMAX];
__device__ int   g_bsum[64];
__device__ int   g_boff[64];
__device__ int   g_scan_ctr;

// ---------------- CSR build ----------------
__global__ void zero_cnt_kernel(int n) {
    int i = blockIdx.x * blockDim.x + threadIdx.x;
    if (i < n + 8) g_cnt[i] = 0;
    if (i == 0) g_scan_ctr = 0;          // reset publish counter every launch (replay-safe)
}

// 4 edges per thread (int4 loads; E known multiple of 4, tail handled anyway)
__global__ void count_kernel(const int* __restrict__ dst, int e) {
    int i = (blockIdx.x * blockDim.x + threadIdx.x) * 4;
    if (i + 4 <= e) {
        int4 d = *(const int4*)(dst + i);
        atomicAdd(&g_cnt[d.x], 1);
        atomicAdd(&g_cnt[d.y], 1);
        atomicAdd(&g_cnt[d.z], 1);
        atomicAdd(&g_cnt[d.w], 1);
    } else {
        for (; i < e; i++) atomicAdd(&g_cnt[dst[i]], 1);
    }
}

// Stage 1 + fused stage 2: per-block sums; last block to finish publishes exclusive offsets.
__global__ __launch_bounds__(256) void scan1_kernel(int n, int nb, int e_total) {
    __shared__ int red[256];
    int b = blockIdx.x, t = threadIdx.x;
    int base = b * SCAN_BS + t * 8;
    int s = 0;
    if (base + 8 <= n) {
        int4 a = *(const int4*)&g_cnt[base];
        int4 c = *(const int4*)&g_cnt[base + 4];
        s = a.x + a.y + a.z + a.w + c.x + c.y + c.z + c.w;
    } else {
        for (int i = 0; i < 8; i++) {
            int idx = base + i;
            if (idx < n) s += g_cnt[idx];
        }
    }
    red[t] = s;
    __syncthreads();
    for (int off = 128; off > 0; off >>= 1) {
        if (t < off) red[t] += red[t + off];
        __syncthreads();
    }
    if (t == 0) {
        g_bsum[b] = red[0];
        __threadfence();
        int done = atomicAdd(&g_scan_ctr, 1);
        if (done == nb - 1) {            // last arriving block publishes the serial scan
            int acc = 0;
            for (int i = 0; i < nb; i++) {
                g_boff[i] = acc;
                acc += g_bsum[i];
            }
            g_rowstart[n] = e_total;
            __threadfence();
        }
    }
}

__global__ __launch_bounds__(256) void scan3_kernel(int n) {
    __shared__ int sh[256];
    int b = blockIdx.x, t = threadIdx.x;
    int base = b * SCAN_BS + t * 8;
    int loc[8];
    int s = 0;
    if (base + 8 <= n) {
        int4 a = *(const int4*)&g_cnt[base];
        int4 c = *(const int4*)&g_cnt[base + 4];
        loc[0] = a.x; loc[1] = a.y; loc[2] = a.z; loc[3] = a.w;
        loc[4] = c.x; loc[5] = c.y; loc[6] = c.z; loc[7] = c.w;
        s = a.x + a.y + a.z + a.w + c.x + c.y + c.z + c.w;
    } else {
#pragma unroll
        for (int i = 0; i < 8; i++) {
            int idx = base + i;
            loc[i] = (idx < n) ? g_cnt[idx] : 0;
            s += loc[i];
        }
    }
    sh[t] = s;
    __syncthreads();
    for (int off = 1; off < 256; off <<= 1) {
        int v = (t >= off) ? sh[t - off] : 0;
        __syncthreads();
        sh[t] += v;
        __syncthreads();
    }
    int pre = g_boff[b] + ((t > 0) ? sh[t - 1] : 0);
    if (base + 8 <= n) {
        int rs[8];
        float dv[8];
#pragma unroll
        for (int i = 0; i < 8; i++) {
            rs[i] = pre;
            dv[i] = rsqrtf((float)(loc[i] + 1));
            pre += loc[i];
        }
        *(int4*)&g_rowstart[base]     = make_int4(rs[0], rs[1], rs[2], rs[3]);
        *(int4*)&g_rowstart[base + 4] = make_int4(rs[4], rs[5], rs[6], rs[7]);
        *(int4*)&g_cursor[base]       = make_int4(rs[0], rs[1], rs[2], rs[3]);
        *(int4*)&g_cursor[base + 4]   = make_int4(rs[4], rs[5], rs[6], rs[7]);
        *(float4*)&g_dinv[base]       = make_float4(dv[0], dv[1], dv[2], dv[3]);
        *(float4*)&g_dinv[base + 4]   = make_float4(dv[4], dv[5], dv[6], dv[7]);
    } else {
#pragma unroll
        for (int i = 0; i < 8; i++) {
            int idx = base + i;
            if (idx < n) {
                g_rowstart[idx] = pre;
                g_cursor[idx]   = pre;
                g_dinv[idx]     = rsqrtf((float)(loc[i] + 1));
                pre += loc[i];
            }
        }
    }
}

// 4 edges per thread
__global__ void place_kernel(const int* __restrict__ src, const int* __restrict__ dst, int e) {
    int i = (blockIdx.x * blockDim.x + threadIdx.x) * 4;
    if (i + 4 <= e) {
        int4 sv = *(const int4*)(src + i);
        int4 dv = *(const int4*)(dst + i);
        int p0 = atomicAdd(&g_cursor[dv.x], 1);
        int p1 = atomicAdd(&g_cursor[dv.y], 1);
        int p2 = atomicAdd(&g_cursor[dv.z], 1);
        int p3 = atomicAdd(&g_cursor[dv.w], 1);
        g_csrc[p0] = sv.x;
        g_csrc[p1] = sv.y;
        g_csrc[p2] = sv.z;
        g_csrc[p3] = sv.w;
    } else {
        for (; i < e; i++) {
            int p = atomicAdd(&g_cursor[dst[i]], 1);
            g_csrc[p] = src[i];
        }
    }
}

// ---------------- weight conversions ----------------
__global__ void convert_w_kernel(const float* __restrict__ W, __half* __restrict__ Wh) {
    int i = (blockIdx.x * 256 + threadIdx.x) * 4;
    if (i < FDIM * FDIM) {
        float4 v = *(const float4*)(W + i);
        __half2 h0 = __floats2half2_rn(v.x, v.y);
        __half2 h1 = __floats2half2_rn(v.z, v.w);
        *(uint2*)(Wh + i) = make_uint2(*(unsigned*)&h0, *(unsigned*)&h1);
    }
}

__global__ void convert_wc_kernel(const float* __restrict__ Wc, __half* __restrict__ Wch) {
    int i = blockIdx.x * 256 + threadIdx.x;
    if (i < FDIM * 48) {
        int row = i / 48, col = i % 48;
        float v = (col < 40) ? Wc[row * 40 + col] : 0.0f;
        Wch[i] = __float2half_rn(v);
    }
}

// ---------------- TC GEMM (A fp32): H = fp16(A @ Wh) ----------------
__global__ __launch_bounds__(256) void gemm_tc_f32(const float* __restrict__ A,
                                                   const __half* __restrict__ Wh,
                                                   __half* __restrict__ H, int n) {
    __shared__ __align__(16) __half As[128][144];
    __shared__ __align__(16) float  St[8][16][20];
    int t = threadIdx.x;
    int wid = t >> 5, lane = t & 31;
    int m0 = blockIdx.x * 128;

#pragma unroll
    for (int it = 0; it < 16; it++) {
        int flat = (it * 256 + t) * 4;
        int row = flat >> 7, col = flat & 127;
        float4 v = make_float4(0.f, 0.f, 0.f, 0.f);
        if (m0 + row < n)
            v = *(const float4*)(A + (size_t)(m0 + row) * 128 + col);
        __half2 h0 = __floats2half2_rn(v.x, v.y);
        __half2 h1 = __floats2half2_rn(v.z, v.w);
        *(uint2*)&As[row][col] = make_uint2(*(unsigned*)&h0, *(unsigned*)&h1);
    }
    __syncthreads();

    int warp_m = wid >> 2;
    int warp_n = wid & 3;

    wmma::fragment<wmma::accumulator, 16, 16, 16, float> c[4][2];
#pragma unroll
    for (int i = 0; i < 4; i++)
#pragma unroll
        for (int j = 0; j < 2; j++) wmma::fill_fragment(c[i][j], 0.0f);

#pragma unroll
    for (int kk = 0; kk < 128; kk += 16) {
        wmma::fragment<wmma::matrix_a, 16, 16, 16, __half, wmma::row_major> a[4];
        wmma::fragment<wmma::matrix_b, 16, 16, 16, __half, wmma::row_major> b[2];
#pragma unroll
        for (int i = 0; i < 4; i++)
            wmma::load_matrix_sync(a[i], &As[warp_m * 64 + i * 16][kk], 144);
#pragma unroll
        for (int j = 0; j < 2; j++)
            wmma::load_matrix_sync(b[j], Wh + (size_t)kk * 128 + warp_n * 32 + j * 16, 128);
#pragma unroll
        for (int i = 0; i < 4; i++)
#pragma unroll
            for (int j = 0; j < 2; j++)
                wmma::mma_sync(c[i][j], a[i], b[j], c[i][j]);
    }

#pragma unroll
    for (int i = 0; i < 4; i++) {
#pragma unroll
        for (int j = 0; j < 2; j++) {
            wmma::store_matrix_sync(&St[wid][0][0], c[i][j], 20, wmma::mem_row_major);
            __syncwarp();
            int r = lane >> 1;
            int cbase = (lane & 1) * 8;
            int grow = m0 + warp_m * 64 + i * 16 + r;
            if (grow < n) {
                __half hbuf[8];
#pragma unroll
                for (int q = 0; q < 8; q++) hbuf[q] = __float2half_rn(St[wid][r][cbase + q]);
                *(uint4*)(H + (size_t)grow * 128 + warp_n * 32 + j * 16 + cbase) = *(uint4*)hbuf;
            }
            __syncwarp();
        }
    }
}

// ---------------- TC GEMM (A fp16): H = fp16(A @ Wh) ----------------
__global__ __launch_bounds__(256) void gemm_tc_f16(const __half* __restrict__ A,
                                                   const __half* __restrict__ Wh,
                                                   __half* __restrict__ H, int n) {
    __shared__ __align__(16) __half As[128][144];
    __shared__ __align__(16) float  St[8][16][20];
    int t = threadIdx.x;
    int wid = t >> 5, lane = t & 31;
    int m0 = blockIdx.x * 128;

#pragma unroll
    for (int it = 0; it < 8; it++) {
        int flat = (it * 256 + t) * 8;     // in halves
        int row = flat >> 7, col = flat & 127;
        uint4 v = make_uint4(0, 0, 0, 0);
        if (m0 + row < n)
            v = *(const uint4*)(A + (size_t)(m0 + row) * 128 + col);
        *(uint4*)&As[row][col] = v;
    }
    __syncthreads();

    int warp_m = wid >> 2;
    int warp_n = wid & 3;

    wmma::fragment<wmma::accumulator, 16, 16, 16, float> c[4][2];
#pragma unroll
    for (int i = 0; i < 4; i++)
#pragma unroll
        for (int j = 0; j < 2; j++) wmma::fill_fragment(c[i][j], 0.0f);

#pragma unroll
    for (int kk = 0; kk < 128; kk += 16) {
        wmma::fragment<wmma::matrix_a, 16, 16, 16, __half, wmma::row_major> a[4];
        wmma::fragment<wmma::matrix_b, 16, 16, 16, __half, wmma::row_major> b[2];
#pragma unroll
        for (int i = 0; i < 4; i++)
            wmma::load_matrix_sync(a[i], &As[warp_m * 64 + i * 16][kk], 144);
#pragma unroll
        for (int j = 0; j < 2; j++)
            wmma::load_matrix_sync(b[j], Wh + (size_t)kk * 128 + warp_n * 32 + j * 16, 128);
#pragma unroll
        for (int i = 0; i < 4; i++)
#pragma unroll
            for (int j = 0; j < 2; j++)
                wmma::mma_sync(c[i][j], a[i], b[j], c[i][j]);
    }

#pragma unroll
    for (int i = 0; i < 4; i++) {
#pragma unroll
        for (int j = 0; j < 2; j++) {
            wmma::store_matrix_sync(&St[wid][0][0], c[i][j], 20, wmma::mem_row_major);
            __syncwarp();
            int r = lane >> 1;
            int cbase = (lane & 1) * 8;
            int grow = m0 + warp_m * 64 + i * 16 + r;
            if (grow < n) {
                __half hbuf[8];
#pragma unroll
                for (int q = 0; q < 8; q++) hbuf[q] = __float2half_rn(St[wid][r][cbase + q]);
                *(uint4*)(H + (size_t)grow * 128 + warp_n * 32 + j * 16 + cbase) = *(uint4*)hbuf;
            }
            __syncwarp();
        }
    }
}

// ---------------- Aggregation: warp/node, fp16 gathers, fp32 acc, fp16 out ----------------
__global__ __launch_bounds__(256) void aggregate_kernel(const __half* __restrict__ H,
                                                        const float* __restrict__ bias,
                                                        __half* O, const __half* resid,
                                                        int has_resid, int n) {
    int warp = (blockIdx.x * blockDim.x + threadIdx.x) >> 5;
    int lane = threadIdx.x & 31;
    if (warp >= n) return;
    int s = g_rowstart[warp];
    int e = g_rowstart[warp + 1];
    const uint2* H8 = (const uint2*)H;
    size_t self = (size_t)warp * 32 + lane;
    float d = g_dinv[warp];

    uint2 raw = H8[self];
    float2 f0 = __half22float2(*(__half2*)&raw.x), f1 = __half22float2(*(__half2*)&raw.y);
    float4 acc = make_float4(f0.x * d, f0.y * d, f1.x * d, f1.y * d);

    int i = s;
    for (; i + 3 < e; i += 4) {
        int j0 = g_csrc[i];
        int j1 = g_csrc[i + 1];
        int j2 = g_csrc[i + 2];
        int j3 = g_csrc[i + 3];
        float d0 = g_dinv[j0], d1 = g_dinv[j1], d2 = g_dinv[j2], d3 = g_dinv[j3];
        uint2 r0 = H8[(size_t)j0 * 32 + lane];
        uint2 r1 = H8[(size_t)j1 * 32 + lane];
        uint2 r2 = H8[(size_t)j2 * 32 + lane];
        uint2 r3 = H8[(size_t)j3 * 32 + lane];
        {
            float2 a = __half22float2(*(__half2*)&r0.x), b = __half22float2(*(__half2*)&r0.y);
            acc.x = fmaf(a.x, d0, acc.x); acc.y = fmaf(a.y, d0, acc.y);
            acc.z = fmaf(b.x, d0, acc.z); acc.w = fmaf(b.y, d0, acc.w);
        }
        {
            float2 a = __half22float2(*(__half2*)&r1.x), b = __half22float2(*(__half2*)&r1.y);
            acc.x = fmaf(a.x, d1, acc.x); acc.y = fmaf(a.y, d1, acc.y);
            acc.z = fmaf(b.x, d1, acc.z); acc.w = fmaf(b.y, d1, acc.w);
        }
        {
            float2 a = __half22float2(*(__half2*)&r2.x), b = __half22float2(*(__half2*)&r2.y);
            acc.x = fmaf(a.x, d2, acc.x); acc.y = fmaf(a.y, d2, acc.y);
            acc.z = fmaf(b.x, d2, acc.z); acc.w = fmaf(b.y, d2, acc.w);
        }
        {
            float2 a = __half22float2(*(__half2*)&r3.x), b = __half22float2(*(__half2*)&r3.y);
            acc.x = fmaf(a.x, d3, acc.x); acc.y = fmaf(a.y, d3, acc.y);
            acc.z = fmaf(b.x, d3, acc.z); acc.w = fmaf(b.y, d3, acc.w);
        }
    }
    for (; i < e; i++) {
        int j = g_csrc[i];
        float dj = g_dinv[j];
        uint2 r = H8[(size_t)j * 32 + lane];
        float2 a = __half22float2(*(__half2*)&r.x), b = __half22float2(*(__half2*)&r.y);
        acc.x = fmaf(a.x, dj, acc.x); acc.y = fmaf(a.y, dj, acc.y);
        acc.z = fmaf(b.x, dj, acc.z); acc.w = fmaf(b.y, dj, acc.w);
    }

    float4 b = ((const float4*)bias)[lane];
    acc.x = fmaxf(fmaf(acc.x, d, b.x), 0.f);
    acc.y = fmaxf(fmaf(acc.y, d, b.y), 0.f);
    acc.z = fmaxf(fmaf(acc.z, d, b.z), 0.f);
    acc.w = fmaxf(fmaf(acc.w, d, b.w), 0.f);
    if (has_resid) {
        uint2 rr = ((const uint2*)resid)[self];
        float2 a = __half22float2(*(__half2*)&rr.x), c = __half22float2(*(__half2*)&rr.y);
        acc.x += a.x; acc.y += a.y; acc.z += c.x; acc.w += c.y;
    }
    __half2 o0 = __floats2half2_rn(acc.x, acc.y);
    __half2 o1 = __floats2half2_rn(acc.z, acc.w);
    ((uint2*)O)[self] = make_uint2(*(unsigned*)&o0, *(unsigned*)&o1);
}

// ---------------- Output GEMM (TC): out = S @ Wch + bc ----------------
__global__ __launch_bounds__(256) void gemm_out_tc(const __half* __restrict__ S,
                                                   const __half* __restrict__ Wch,
                                                   const float* __restrict__ bc,
                                                   float* __restrict__ out, int n) {
    __shared__ __align__(16) float St[8][16][48];
    __shared__ float bs[48];
    int t = threadIdx.x;
    int w = t >> 5, lane = t & 31;
    if (t < 48) bs[t] = (t < 40) ? bc[t] : 0.0f;
    __syncthreads();

    int row0 = blockIdx.x * 128 + w * 16;

    wmma::fragment<wmma::accumulator, 16, 16, 16, float> c[3];
#pragma unroll
    for (int j = 0; j < 3; j++) wmma::fill_fragment(c[j], 0.0f);

#pragma unroll
    for (int kk = 0; kk < 128; kk += 16) {
        wmma::fragment<wmma::matrix_a, 16, 16, 16, __half, wmma::row_major> a;
        wmma::load_matrix_sync(a, S + (size_t)row0 * 128 + kk, 128);
        wmma::fragment<wmma::matrix_b, 16, 16, 16, __half, wmma::row_major> b[3];
#pragma unroll
        for (int j = 0; j < 3; j++)
            wmma::load_matrix_sync(b[j], Wch + (size_t)kk * 48 + j * 16, 48);
#pragma unroll
        for (int j = 0; j < 3; j++)
            wmma::mma_sync(c[j], a, b[j], c[j]);
    }

#pragma unroll
    for (int j = 0; j < 3; j++)
        wmma::store_matrix_sync(&St[w][0][j * 16], c[j], 48, wmma::mem_row_major);
    __syncwarp();

    int r = lane >> 1;
    int cb = (lane & 1) * 20;
    int grow = row0 + r;
    if (grow < n) {
#pragma unroll
        for (int q = 0; q < 5; q++) {
            float4 v;
            v.x = St[w][r][cb + q * 4 + 0] + bs[cb + q * 4 + 0];
            v.y = St[w][r][cb + q * 4 + 1] + bs[cb + q * 4 + 1];
            v.z = St[w][r][cb + q * 4 + 2] + bs[cb + q * 4 + 2];
            v.w = St[w][r][cb + q * 4 + 3] + bs[cb + q * 4 + 3];
            *(float4*)(out + (size_t)grow * 40 + cb + q * 4) = v;
        }
    }
}

// ---------------- launch (serial main chain; CSR forked under GEMM1) ----------------
extern "C" void kernel_launch(void* const* d_in, const int* in_sizes, int n_in,
                              void* d_out, int out_size) {
    const float* x  = (const float*)d_in[0];
    const float* W1 = (const float*)d_in[1];
    const float* b1 = (const float*)d_in[2];
    const float* W2 = (const float*)d_in[3];
    const float* b2 = (const float*)d_in[4];
    const float* Wc = (const float*)d_in[5];
    const float* bc = (const float*)d_in[6];
    const int*   ei = (const int*)d_in[7];

    int N = in_sizes[0] / FDIM;
    int E = in_sizes[7] / 2;
    if (N > NMAX) N = NMAX;
    if (E > EMAX) E = EMAX;
    const int* src = ei;
    const int* dst = ei + E;

    __half *H, *O1, *W1h, *W2h, *Wch;
    cudaGetSymbolAddress((void**)&H,   g_bufH);
    cudaGetSymbolAddress((void**)&O1,  g_bufO1);
    cudaGetSymbolAddress((void**)&W1h, g_W1h);
    cudaGetSymbolAddress((void**)&W2h, g_W2h);
    cudaGetSymbolAddress((void**)&Wch, g_Wch);

    static cudaStream_t s2 = nullptr;
    static cudaEvent_t ev_fork = nullptr, ev_csr = nullptr;
    if (s2 == nullptr) {
        cudaStreamCreateWithFlags(&s2, cudaStreamNonBlocking);
        cudaEventCreateWithFlags(&ev_fork, cudaEventDisableTiming);
        cudaEventCreateWithFlags(&ev_csr, cudaEventDisableTiming);
    }

    int nscanblk  = (N + SCAN_BS - 1) / SCAN_BS;
    int gemm_grid = (N + 127) / 128;
    int agg_grid  = (N * 32 + 255) / 256;
    int e4_grid   = (E / 4 + 256) / 256;   // 4 edges/thread (covers tail)

    // Fork: CSR build on s2, concurrent with W conversion + GEMM1 on stream 0.
    cudaEventRecord(ev_fork, 0);
    cudaStreamWaitEvent(s2, ev_fork, 0);
    zero_cnt_kernel<<<(N + 8 + 255) / 256, 256, 0, s2>>>(N);
    count_kernel<<<e4_grid, 256, 0, s2>>>(dst, E);
    scan1_kernel<<<nscanblk, 256, 0, s2>>>(N, nscanblk, E);   // fused block-sum + publish
    scan3_kernel<<<nscanblk, 256, 0, s2>>>(N);
    place_kernel<<<e4_grid, 256, 0, s2>>>(src, dst, E);
    cudaEventRecord(ev_csr, s2);

    // Weight conversions + Layer 1 GEMM on stream 0.
    convert_w_kernel<<<16, 256>>>(W1, W1h);
    convert_w_kernel<<<16, 256>>>(W2, W2h);
    convert_wc_kernel<<<24, 256>>>(Wc, Wch);
    gemm_tc_f32<<<gemm_grid, 256>>>(x, W1h, H, N);

    // Join, then serial main chain (all intermediates fp16).
    cudaStreamWaitEvent(0, ev_csr, 0);
    aggregate_kernel<<<agg_grid, 256>>>(H, b1, O1, nullptr, 0, N);   // out1 (fp16)
    gemm_tc_f16<<<gemm_grid, 256>>>(O1, W2h, H, N);                  // h2 (fp16)
    aggregate_kernel<<<agg_grid, 256>>>(H, b2, O1, O1, 1, N);        // s = out2+out1 (in-place fp16)
    gemm_out_tc<<<gemm_grid, 256>>>(O1, Wch, bc, (float*)d_out, N);  // out fp32
}